// round 4
// baseline (speedup 1.0000x reference)
#include <cuda_runtime.h>

#define BB 8
#define SS 2048
#define HH 1024
#define NT (BB * SS)   // 16384 tokens
#define RPB 8          // pair rows per block

// Scratch (device globals — no allocation allowed in kernel_launch)
__device__ float g_ss[NT];      // score_s per token
__device__ float g_se[NT];      // score_e per token (+ bm folded in)
__device__ int   g_fl[NT];      // bit0 = start_cand, bit1 = end_cand

// ---------------------------------------------------------------------------
// Kernel 1: 512 threads = 16 warps; each warp processes 4 tokens -> 64
// tokens/block, 256 blocks. Weights folded into smem once per block; each
// LDS.128 weight load is reused for 4 rep rows (smem traffic /4), and the
// 4 independent rep LDG.128s per iter give MLP=4..8. DRAM-read bound: 64 MB.
// ---------------------------------------------------------------------------
__global__ void __launch_bounds__(512)
logits_kernel(const float* __restrict__ rep,
              const int*   __restrict__ mask,
              const float* __restrict__ Ws,  const float* __restrict__ bs,
              const float* __restrict__ We,  const float* __restrict__ be,
              const float* __restrict__ Wm,  const float* __restrict__ bm)
{
    __shared__ float s_wds[HH];   // Ws[:,1]-Ws[:,0]
    __shared__ float s_wss[HH];   // Wm0*Ws[:,0]+Wm1*Ws[:,1]
    __shared__ float s_wde[HH];   // We[:,1]-We[:,0]
    __shared__ float s_wse[HH];   // Wm2*We[:,0]+Wm3*We[:,1]
    __shared__ float s_bias[4];

    const int tid = threadIdx.x;
    {
        const float wm0 = Wm[0], wm1 = Wm[1], wm2 = Wm[2], wm3 = Wm[3];
        #pragma unroll
        for (int p = 0; p < HH / 512; p++) {
            int h = p * 512 + tid;
            float a0 = Ws[2 * h], a1 = Ws[2 * h + 1];
            float c0 = We[2 * h], c1 = We[2 * h + 1];
            s_wds[h] = a1 - a0;
            s_wss[h] = wm0 * a0 + wm1 * a1;
            s_wde[h] = c1 - c0;
            s_wse[h] = wm2 * c0 + wm3 * c1;
        }
        if (tid == 0) {
            s_bias[0] = bs[1] - bs[0];
            s_bias[1] = wm0 * bs[0] + wm1 * bs[1];
            s_bias[2] = be[1] - be[0];
            s_bias[3] = wm2 * be[0] + wm3 * be[1] + bm[0];
        }
    }
    __syncthreads();

    const int warp = tid >> 5;
    const int lane = tid & 31;
    const int t0   = blockIdx.x * 64 + warp * 4;   // first of 4 tokens

    const float4* r40 = reinterpret_cast<const float4*>(rep + (size_t)(t0 + 0) * HH);
    const float4* r41 = reinterpret_cast<const float4*>(rep + (size_t)(t0 + 1) * HH);
    const float4* r42 = reinterpret_cast<const float4*>(rep + (size_t)(t0 + 2) * HH);
    const float4* r43 = reinterpret_cast<const float4*>(rep + (size_t)(t0 + 3) * HH);

    const float4* wds = reinterpret_cast<const float4*>(s_wds);
    const float4* wss = reinterpret_cast<const float4*>(s_wss);
    const float4* wde = reinterpret_cast<const float4*>(s_wde);
    const float4* wse = reinterpret_cast<const float4*>(s_wse);

    float ds[4] = {0,0,0,0}, sv[4] = {0,0,0,0}, de[4] = {0,0,0,0}, se[4] = {0,0,0,0};

    #pragma unroll 2
    for (int k = 0; k < HH / 128; k++) {
        int idx = k * 32 + lane;
        float4 r0 = __ldcs(&r40[idx]);
        float4 r1 = __ldcs(&r41[idx]);
        float4 r2 = __ldcs(&r42[idx]);
        float4 r3 = __ldcs(&r43[idx]);
        float4 a = wds[idx];
        float4 b = wss[idx];
        float4 c = wde[idx];
        float4 d = wse[idx];

        ds[0] += r0.x*a.x + r0.y*a.y + r0.z*a.z + r0.w*a.w;
        sv[0] += r0.x*b.x + r0.y*b.y + r0.z*b.z + r0.w*b.w;
        de[0] += r0.x*c.x + r0.y*c.y + r0.z*c.z + r0.w*c.w;
        se[0] += r0.x*d.x + r0.y*d.y + r0.z*d.z + r0.w*d.w;

        ds[1] += r1.x*a.x + r1.y*a.y + r1.z*a.z + r1.w*a.w;
        sv[1] += r1.x*b.x + r1.y*b.y + r1.z*b.z + r1.w*b.w;
        de[1] += r1.x*c.x + r1.y*c.y + r1.z*c.z + r1.w*c.w;
        se[1] += r1.x*d.x + r1.y*d.y + r1.z*d.z + r1.w*d.w;

        ds[2] += r2.x*a.x + r2.y*a.y + r2.z*a.z + r2.w*a.w;
        sv[2] += r2.x*b.x + r2.y*b.y + r2.z*b.z + r2.w*b.w;
        de[2] += r2.x*c.x + r2.y*c.y + r2.z*c.z + r2.w*c.w;
        se[2] += r2.x*d.x + r2.y*d.y + r2.z*d.z + r2.w*d.w;

        ds[3] += r3.x*a.x + r3.y*a.y + r3.z*a.z + r3.w*a.w;
        sv[3] += r3.x*b.x + r3.y*b.y + r3.z*b.z + r3.w*b.w;
        de[3] += r3.x*c.x + r3.y*c.y + r3.z*c.z + r3.w*c.w;
        se[3] += r3.x*d.x + r3.y*d.y + r3.z*d.z + r3.w*d.w;
    }

    #pragma unroll
    for (int tt = 0; tt < 4; tt++) {
        float x0 = ds[tt], x1 = sv[tt], x2 = de[tt], x3 = se[tt];
        #pragma unroll
        for (int off = 16; off; off >>= 1) {
            x0 += __shfl_xor_sync(0xffffffffu, x0, off);
            x1 += __shfl_xor_sync(0xffffffffu, x1, off);
            x2 += __shfl_xor_sync(0xffffffffu, x2, off);
            x3 += __shfl_xor_sync(0xffffffffu, x3, off);
        }
        if (lane == 0) {
            int t  = t0 + tt;
            int m  = (mask[t] != 0);
            int sc = m && ((x0 + s_bias[0]) >= 0.f);   // s0 <= s1
            int ec = m && ((x2 + s_bias[2]) >= 0.f);   // e0 <= e1
            g_ss[t] = x1 + s_bias[1];
            g_se[t] = x3 + s_bias[3];
            g_fl[t] = sc | (ec << 1);
        }
    }
}

// ---------------------------------------------------------------------------
// Kernel 2: one block per 8 rows of one batch. se4/fl4 for this thread's 4
// columns are loaded ONCE into registers and reused for all 8 rows ->
// L2 read traffic drops 256MB -> 32MB, freeing LTS for the 268MB of stores.
// ---------------------------------------------------------------------------
__global__ void __launch_bounds__(512)
pair_kernel(float* __restrict__ out_valid,
            float* __restrict__ out_masked)
{
    const int b  = blockIdx.y;
    const int i0 = blockIdx.x * RPB;
    const int j4 = threadIdx.x;
    const int j0 = j4 * 4;

    const float4 se4 = reinterpret_cast<const float4*>(g_se + b * SS)[j4];
    const int4   fl4 = reinterpret_cast<const int4*>(g_fl + b * SS)[j4];
    const bool   e0 = fl4.x & 2, e1 = fl4.y & 2, e2 = fl4.z & 2, e3 = fl4.w & 2;

    float ssv[RPB];
    int   scv[RPB];
    #pragma unroll
    for (int r = 0; r < RPB; r++) {
        int t = b * SS + i0 + r;
        ssv[r] = g_ss[t];
        scv[r] = g_fl[t] & 1;
    }

    #pragma unroll
    for (int r = 0; r < RPB; r++) {
        const int i = i0 + r;
        const size_t rowoff = ((size_t)b * SS + i) * SS;
        float4* ov = reinterpret_cast<float4*>(out_valid  + rowoff) + j4;
        float4* om = reinterpret_cast<float4*>(out_masked + rowoff) + j4;

        float4 v, m;
        if (!scv[r] || (j0 + 3) < i) {
            v = make_float4(0.f, 0.f, 0.f, 0.f);
            m = v;
        } else {
            const float ss = ssv[r];
            float ps; bool val;
            ps = ss + se4.x; val = e0 && (i <= j0 + 0) && (ps > 0.f);
            v.x = val ? 1.f : 0.f; m.x = val ? ps : 0.f;
            ps = ss + se4.y; val = e1 && (i <= j0 + 1) && (ps > 0.f);
            v.y = val ? 1.f : 0.f; m.y = val ? ps : 0.f;
            ps = ss + se4.z; val = e2 && (i <= j0 + 2) && (ps > 0.f);
            v.z = val ? 1.f : 0.f; m.z = val ? ps : 0.f;
            ps = ss + se4.w; val = e3 && (i <= j0 + 3) && (ps > 0.f);
            v.w = val ? 1.f : 0.f; m.w = val ? ps : 0.f;
        }
        __stcs(ov, v);
        __stcs(om, m);
    }
}

extern "C" void kernel_launch(void* const* d_in, const int* in_sizes, int n_in,
                              void* d_out, int out_size)
{
    const float* rep  = (const float*)d_in[0];
    const int*   mask = (const int*)  d_in[1];
    const float* Ws   = (const float*)d_in[2];
    const float* bs   = (const float*)d_in[3];
    const float* We   = (const float*)d_in[4];
    const float* be   = (const float*)d_in[5];
    const float* Wm   = (const float*)d_in[6];
    const float* bm   = (const float*)d_in[7];

    float* out = (float*)d_out;
    const size_t half = (size_t)BB * SS * SS;   // valid first, masked second

    logits_kernel<<<NT / 64, 512>>>(rep, mask, Ws, bs, We, be, Wm, bm);

    dim3 g2(SS / RPB, BB);
    pair_kernel<<<g2, 512>>>(out, out + half);
}